// round 3
// baseline (speedup 1.0000x reference)
#include <cuda_runtime.h>

// DynamicTopGate: h = tanh(x @ W1^T); logits = (h @ W2^T)/0.7; full argsort of
// 16 logits; softmax; cumulative-prob dynamic-k; outputs (idx, scores, mask, k)
// concatenated as float32 into d_out: [B*8 | B*8 | B*8 | B].
//
// Shapes: x[B=16384, 2048] f32, W1[16, 2048] f32, W2[16,16] f32.

#define IN_DIM 2048
#define NE     16

typedef unsigned long long u64;

// Packed f32x2 FMA (Blackwell sm_100+): 2 FMAs per instruction.
__device__ __forceinline__ u64 ffma2(u64 a, u64 b, u64 c) {
    u64 d;
    asm("fma.rn.f32x2 %0, %1, %2, %3;" : "=l"(d) : "l"(a), "l"(b), "l"(c));
    return d;
}

__device__ __forceinline__ void unpack2(u64 a, float& lo, float& hi) {
    asm("mov.b64 {%0, %1}, %2;" : "=f"(lo), "=f"(hi) : "l"(a));
}

// Descending compare-exchange with stable (index-ascending) tie-break,
// matching jnp.argsort(-logits) semantics.
#define CE(a, b) do {                                                \
    float va = v[a], vb = v[b]; int ia = id[a], ib = id[b];          \
    bool sw = (vb > va) || (vb == va && ib < ia);                    \
    v[a] = sw ? vb : va; v[b] = sw ? va : vb;                        \
    id[a] = sw ? ib : ia; id[b] = sw ? ia : ib;                      \
} while (0);

__global__ void __launch_bounds__(128, 3)
gate_kernel(const float* __restrict__ x, const float* __restrict__ W1,
            const float* __restrict__ W2, float* __restrict__ out, int B)
{
    const int lane = threadIdx.x & 31;
    const int gw   = blockIdx.x * (blockDim.x >> 5) + (threadIdx.x >> 5);
    const int row0 = gw * 4;
    if (row0 >= B) return;

    const float4* xp = reinterpret_cast<const float4*>(x + (size_t)row0 * IN_DIM) + lane;
    const float4* wp = reinterpret_cast<const float4*>(W1) + lane;

    // acc[r][e]: packed (even-col sum, odd-col sum) for row r, expert e.
    u64 acc[4][NE];
    #pragma unroll
    for (int r = 0; r < 4; ++r)
        #pragma unroll
        for (int e = 0; e < NE; ++e) acc[r][e] = 0ull;

    // 16 chunks of 128 columns (32 lanes x float4).
    #pragma unroll 1
    for (int c = 0; c < IN_DIM / 128; ++c) {
        u64 xl[4], xh[4];
        #pragma unroll
        for (int r = 0; r < 4; ++r) {
            float4 xv = __ldcs(xp + r * (IN_DIM / 4) + c * 32);   // streaming: keep W1 in L1
            const u64* pv = reinterpret_cast<const u64*>(&xv);
            xl[r] = pv[0]; xh[r] = pv[1];
        }
        #pragma unroll
        for (int e = 0; e < NE; ++e) {
            float4 wv = __ldg(wp + e * (IN_DIM / 4) + c * 32);    // L1-resident, reused by all warps
            const u64* pw = reinterpret_cast<const u64*>(&wv);
            u64 wl = pw[0], wh = pw[1];
            #pragma unroll
            for (int r = 0; r < 4; ++r) acc[r][e] = ffma2(xl[r], wl, acc[r][e]);
            #pragma unroll
            for (int r = 0; r < 4; ++r) acc[r][e] = ffma2(xh[r], wh, acc[r][e]);
        }
    }

    // Warp-reduce each (row, expert) partial; lane r keeps row r's value.
    float myh[NE];
    #pragma unroll
    for (int e = 0; e < NE; ++e) {
        float s[4];
        #pragma unroll
        for (int r = 0; r < 4; ++r) {
            float lo, hi; unpack2(acc[r][e], lo, hi);
            float t = lo + hi;
            #pragma unroll
            for (int off = 16; off > 0; off >>= 1)
                t += __shfl_xor_sync(0xffffffffu, t, off);
            s[r] = t;
        }
        myh[e] = (lane == 0) ? s[0] : (lane == 1) ? s[1] : (lane == 2) ? s[2] : s[3];
    }

    if (lane < 4) {
        const int row = row0 + lane;

        float h[NE];
        #pragma unroll
        for (int e = 0; e < NE; ++e) h[e] = tanhf(myh[e]);

        // logits[f] = sum_e h[e] * W2[f, e], divided by TEMP=0.7
        float v[NE]; int id[NE];
        const float4* W2v = reinterpret_cast<const float4*>(W2);
        #pragma unroll
        for (int f = 0; f < NE; ++f) {
            float s = 0.0f;
            #pragma unroll
            for (int q = 0; q < NE / 4; ++q) {
                float4 w = __ldg(W2v + f * (NE / 4) + q);
                s = fmaf(h[4 * q + 0], w.x, s);
                s = fmaf(h[4 * q + 1], w.y, s);
                s = fmaf(h[4 * q + 2], w.z, s);
                s = fmaf(h[4 * q + 3], w.w, s);
            }
            v[f] = s / 0.7f;
            id[f] = f;
        }

        // Batcher odd-even mergesort, n=16, 63 comparators, descending.
        CE(0,1) CE(2,3) CE(4,5) CE(6,7) CE(8,9) CE(10,11) CE(12,13) CE(14,15)
        CE(0,2) CE(1,3) CE(4,6) CE(5,7) CE(8,10) CE(9,11) CE(12,14) CE(13,15)
        CE(1,2) CE(5,6) CE(9,10) CE(13,14)
        CE(0,4) CE(1,5) CE(2,6) CE(3,7) CE(8,12) CE(9,13) CE(10,14) CE(11,15)
        CE(2,4) CE(3,5) CE(10,12) CE(11,13)
        CE(1,2) CE(3,4) CE(5,6) CE(9,10) CE(11,12) CE(13,14)
        CE(0,8) CE(1,9) CE(2,10) CE(3,11) CE(4,12) CE(5,13) CE(6,14) CE(7,15)
        CE(4,8) CE(5,9) CE(6,10) CE(7,11)
        CE(2,4) CE(3,5) CE(6,8) CE(7,9) CE(10,12) CE(11,13)
        CE(1,2) CE(3,4) CE(5,6) CE(7,8) CE(9,10) CE(11,12) CE(13,14)

        // Softmax over sorted logits (max = v[0]).
        float m = v[0];
        float p[NE]; float ssum = 0.0f;
        #pragma unroll
        for (int e = 0; e < NE; ++e) { p[e] = expf(v[e] - m); ssum += p[e]; }
        float inv = 1.0f / ssum;
        #pragma unroll
        for (int e = 0; e < NE; ++e) p[e] *= inv;

        // k from cumulative probability.
        int k = NE;
        float cum = 0.0f;
        #pragma unroll
        for (int e = 0; e < NE; ++e) {
            cum += p[e];
            if (k == NE && cum >= 0.92f) k = e + 1;
        }
        float p1 = p[0], p2 = p[1], p3 = p[2];
        if (p1 >= 0.46f && (p1 - p2) >= 0.1f) k = 1;
        if (k > 2 && ((p1 + p2) >= 0.82f || p3 <= 0.12f || (p2 - p3) <= 0.03f)) k = 2;
        if (k < 1) k = 1;
        if (k > 3) k = 3;

        float* oidx  = out;
        float* osc   = out + (size_t)B * 8;
        float* omask = out + (size_t)B * 16;
        float* okv   = out + (size_t)B * 24;
        #pragma unroll
        for (int j = 0; j < 8; ++j) {
            float msk = (j < k) ? 1.0f : 0.0f;
            oidx[row * 8 + j]  = (float)id[j];
            osc[row * 8 + j]   = p[j] * msk;
            omask[row * 8 + j] = msk;
        }
        okv[row] = (float)k;
    }
}

extern "C" void kernel_launch(void* const* d_in, const int* in_sizes, int n_in,
                              void* d_out, int out_size)
{
    const float* x  = (const float*)d_in[0];
    const float* W1 = (const float*)d_in[1];
    const float* W2 = (const float*)d_in[2];
    float* out = (float*)d_out;

    int B = in_sizes[0] / IN_DIM;          // 16384
    int groups = (B + 3) / 4;              // 4 rows per warp
    int warpsPerBlock = 4;                 // 128 threads
    int blocks = (groups + warpsPerBlock - 1) / warpsPerBlock;   // 1024
    gate_kernel<<<blocks, 128>>>(x, W1, W2, out, B);
}